// round 12
// baseline (speedup 1.0000x reference)
#include <cuda_runtime.h>
#include <math.h>
#include <stdint.h>

#define N_NODES 30000
#define N_EDGES 60000
#define FEAT    256
#define HID     1024
#define OUT_DIM 256
#define RANK    64
#define MAX_INC (N_EDGES * 4)

// ---------------- scratch (static device globals; no runtime allocation) ----
__device__ float g_emb_new [(size_t)N_NODES * RANK];
__device__ float g_hid     [(size_t)N_NODES * HID];
__device__ float g_emb_new2[(size_t)N_NODES * OUT_DIM];
__device__ float g_contrib [(size_t)N_EDGES * 4 * OUT_DIM];   // 245.8 MB
__device__ float g_embT    [(size_t)N_NODES * FEAT];
__device__ float g_w1T     [(size_t)FEAT * HID];
__device__ float g_w2T     [(size_t)HID * OUT_DIM];
__device__ float g_waT     [(size_t)FEAT * OUT_DIM];
__device__ float g_deg13   [N_NODES];
__device__ float g_deg14   [N_NODES];
__device__ int   g_offsets [N_NODES];
__device__ int   g_cnt     [N_NODES];
__device__ int   g_idx     [MAX_INC];

__device__ __forceinline__ float tanh_fast(float x)
{
    float y;
    asm("tanh.approx.f32 %0, %1;" : "=f"(y) : "f"(x));
    return y;
}

__device__ __forceinline__ float to_tf32(float x)
{
    uint32_t u;
    asm("cvt.rna.tf32.f32 %0, %1;" : "=r"(u) : "f"(x));
    return __uint_as_float(u);
}

__device__ __forceinline__ void mma_tf32(float d[4], const uint32_t a[4],
                                         const uint32_t b[2])
{
    asm("mma.sync.aligned.m16n8k8.row.col.f32.tf32.tf32.f32 "
        "{%0,%1,%2,%3}, {%4,%5,%6,%7}, {%8,%9}, {%0,%1,%2,%3};"
        : "+f"(d[0]), "+f"(d[1]), "+f"(d[2]), "+f"(d[3])
        : "r"(a[0]), "r"(a[1]), "r"(a[2]), "r"(a[3]),
          "r"(b[0]), "r"(b[1]));
}

__device__ __forceinline__ void cp16(uint32_t dst, const float* src, bool valid)
{
    asm volatile("cp.async.cg.shared.global [%0], [%1], 16, %2;\n"
                 :: "r"(dst), "l"(src), "r"(valid ? 16 : 0));
}
__device__ __forceinline__ void cp_commit()
{
    asm volatile("cp.async.commit_group;\n");
}
template <int N> __device__ __forceinline__ void cp_wait()
{
    asm volatile("cp.async.wait_group %0;\n" :: "n"(N));
}

// ===== tf32 tensor GEMM: R4 layout + cp.async 2-stage, NO in-kernel CVT =====
#define AS_STRIDE 36
#define BS_STRIDE 132
#define AS_SZ (128 * AS_STRIDE)
#define BS_SZ (32 * BS_STRIDE)
#define GEMM_SMEM_BYTES ((2 * AS_SZ + 2 * BS_SZ) * 4)

__global__ __launch_bounds__(256, 2) void gemm_tf32_kernel(
    const float* __restrict__ A, const float* __restrict__ W,
    const float* __restrict__ bias, const float* __restrict__ wrow,
    float* __restrict__ C, int M, int N, int K, int flags)
{
    extern __shared__ float sh[];
    const uint32_t sbase = (uint32_t)__cvta_generic_to_shared(sh);

    const int tid    = threadIdx.x;
    const int lane   = tid & 31;
    const int w      = tid >> 5;
    const int warp_m = w & 1;
    const int warp_n = w >> 1;
    const int g      = lane >> 2;
    const int tg     = lane & 3;
    const int m0     = blockIdx.y * 128;
    const int n0     = blockIdx.x * 128;

    const int a_r  = tid >> 1;
    const int a_c  = (tid & 1) * 16;
    const int b_r  = tid >> 3;
    const int b_c  = (tid & 7) * 16;
    const bool a_ok = (m0 + a_r) < M;

    auto load_tile = [&](int buf, int k0) {
        const uint32_t aoff = sbase +
            (uint32_t)(buf * AS_SZ + a_r * AS_STRIDE + a_c) * 4;
        const float* asrc = A + (size_t)(m0 + a_r) * K + k0 + a_c;
#pragma unroll
        for (int i = 0; i < 4; i++)
            cp16(aoff + 16 * i, asrc + 4 * i, a_ok);
        const uint32_t boff = sbase +
            (uint32_t)(2 * AS_SZ + buf * BS_SZ + b_r * BS_STRIDE + b_c) * 4;
        const float* bsrc = W + (size_t)(k0 + b_r) * N + n0 + b_c;
#pragma unroll
        for (int i = 0; i < 4; i++)
            cp16(boff + 16 * i, bsrc + 4 * i, true);
    };

    float d[4][4][4];
#pragma unroll
    for (int i = 0; i < 4; i++)
#pragma unroll
        for (int j = 0; j < 4; j++)
#pragma unroll
            for (int c = 0; c < 4; c++) d[i][j][c] = 0.f;

    load_tile(0, 0);
    cp_commit();

    int buf = 0;
    for (int k0 = 0; k0 < K; k0 += 32) {
        const bool more = (k0 + 32) < K;
        if (more) { load_tile(buf ^ 1, k0 + 32); cp_commit(); cp_wait<1>(); }
        else      { cp_wait<0>(); }
        __syncthreads();

        const float* Ab = sh + buf * AS_SZ;
        const float* Bb = sh + 2 * AS_SZ + buf * BS_SZ;
#pragma unroll
        for (int ks8 = 0; ks8 < 4; ks8++) {
            const int ks = ks8 * 8;
            uint32_t af[4][4], bf[4][2];
#pragma unroll
            for (int mg = 0; mg < 4; mg++) {
                const int r = warp_m * 64 + mg * 16 + g;
                af[mg][0] = __float_as_uint(Ab[r * AS_STRIDE + ks + tg]);
                af[mg][1] = __float_as_uint(Ab[(r + 8) * AS_STRIDE + ks + tg]);
                af[mg][2] = __float_as_uint(Ab[r * AS_STRIDE + ks + tg + 4]);
                af[mg][3] = __float_as_uint(Ab[(r + 8) * AS_STRIDE + ks + tg + 4]);
            }
#pragma unroll
            for (int ng = 0; ng < 4; ng++) {
                const int cc = warp_n * 32 + ng * 8 + g;
                bf[ng][0] = __float_as_uint(Bb[(ks + tg) * BS_STRIDE + cc]);
                bf[ng][1] = __float_as_uint(Bb[(ks + tg + 4) * BS_STRIDE + cc]);
            }
#pragma unroll
            for (int mg = 0; mg < 4; mg++)
#pragma unroll
                for (int ng = 0; ng < 4; ng++)
                    mma_tf32(d[mg][ng], af[mg], bf[ng]);
        }
        __syncthreads();
        buf ^= 1;
    }

    const bool do_relu  = flags & 1;
    const bool do_round = flags & 2;
#pragma unroll
    for (int mg = 0; mg < 4; mg++) {
        const int r0 = m0 + warp_m * 64 + mg * 16 + g;
#pragma unroll
        for (int ng = 0; ng < 4; ng++) {
            const int col = n0 + warp_n * 32 + ng * 8 + tg * 2;
            float b0 = bias[col]     + (wrow ? wrow[col]     : 0.f);
            float b1 = bias[col + 1] + (wrow ? wrow[col + 1] : 0.f);
            float v0 = d[mg][ng][0] + b0;
            float v1 = d[mg][ng][1] + b1;
            float v2 = d[mg][ng][2] + b0;
            float v3 = d[mg][ng][3] + b1;
            if (do_relu) {
                v0 = fmaxf(v0, 0.f); v1 = fmaxf(v1, 0.f);
                v2 = fmaxf(v2, 0.f); v3 = fmaxf(v3, 0.f);
            }
            if (do_round) {
                v0 = to_tf32(v0); v1 = to_tf32(v1);
                v2 = to_tf32(v2); v3 = to_tf32(v3);
            }
            if (r0 < M)
                *(float2*)(C + (size_t)r0 * N + col) = make_float2(v0, v1);
            if (r0 + 8 < M)
                *(float2*)(C + (size_t)(r0 + 8) * N + col) = make_float2(v2, v3);
        }
    }
}

// ---------------- 64x64 fp32 SGEMM (pW only: accuracy-critical path) --------
#define TM 64
#define TN 64
#define TK 16
#define SST 72

__global__ __launch_bounds__(256) void gemm64_kernel(
    const float* __restrict__ A, const float* __restrict__ W,
    const float* __restrict__ bias, const float* __restrict__ wrow,
    float* __restrict__ C, int M, int N, int K, int do_relu)
{
    __shared__ float As[TK][SST];
    __shared__ float Bs[TK][SST];
    const int tid = threadIdx.x;
    const int tx  = tid & 15;
    const int ty  = tid >> 4;
    const int m0  = blockIdx.y * TM;
    const int n0  = blockIdx.x * TN;

    const int arow = tid >> 2;
    const int acol = (tid & 3) << 2;
    const int brow = tid >> 4;
    const int bcol = (tid & 15) << 2;

    float acc[4][4] = {{0.f,0.f,0.f,0.f},{0.f,0.f,0.f,0.f},
                       {0.f,0.f,0.f,0.f},{0.f,0.f,0.f,0.f}};

    for (int k0 = 0; k0 < K; k0 += TK) {
        float4 av = make_float4(0.f, 0.f, 0.f, 0.f);
        if (m0 + arow < M)
            av = *(const float4*)(A + (size_t)(m0 + arow) * K + k0 + acol);
        As[acol + 0][arow] = av.x;
        As[acol + 1][arow] = av.y;
        As[acol + 2][arow] = av.z;
        As[acol + 3][arow] = av.w;
        *(float4*)&Bs[brow][bcol] =
            *(const float4*)(W + (size_t)(k0 + brow) * N + n0 + bcol);
        __syncthreads();
#pragma unroll
        for (int k = 0; k < TK; k++) {
            float4 a = *(const float4*)&As[k][ty << 2];
            float4 b = *(const float4*)&Bs[k][tx << 2];
            acc[0][0] = fmaf(a.x, b.x, acc[0][0]);
            acc[0][1] = fmaf(a.x, b.y, acc[0][1]);
            acc[0][2] = fmaf(a.x, b.z, acc[0][2]);
            acc[0][3] = fmaf(a.x, b.w, acc[0][3]);
            acc[1][0] = fmaf(a.y, b.x, acc[1][0]);
            acc[1][1] = fmaf(a.y, b.y, acc[1][1]);
            acc[1][2] = fmaf(a.y, b.z, acc[1][2]);
            acc[1][3] = fmaf(a.y, b.w, acc[1][3]);
            acc[2][0] = fmaf(a.z, b.x, acc[2][0]);
            acc[2][1] = fmaf(a.z, b.y, acc[2][1]);
            acc[2][2] = fmaf(a.z, b.z, acc[2][2]);
            acc[2][3] = fmaf(a.z, b.w, acc[2][3]);
            acc[3][0] = fmaf(a.w, b.x, acc[3][0]);
            acc[3][1] = fmaf(a.w, b.y, acc[3][1]);
            acc[3][2] = fmaf(a.w, b.z, acc[3][2]);
            acc[3][3] = fmaf(a.w, b.w, acc[3][3]);
        }
        __syncthreads();
    }

    float bn[4];
#pragma unroll
    for (int j = 0; j < 4; j++) {
        int n = n0 + (tx << 2) + j;
        bn[j] = bias[n] + (wrow ? wrow[n] : 0.f);
    }
#pragma unroll
    for (int i = 0; i < 4; i++) {
        int m = m0 + (ty << 2) + i;
        if (m < M) {
            float4 v;
            v.x = acc[i][0] + bn[0];
            v.y = acc[i][1] + bn[1];
            v.z = acc[i][2] + bn[2];
            v.w = acc[i][3] + bn[3];
            if (do_relu) {
                v.x = fmaxf(v.x, 0.f); v.y = fmaxf(v.y, 0.f);
                v.z = fmaxf(v.z, 0.f); v.w = fmaxf(v.w, 0.f);
            }
            *(float4*)(C + (size_t)m * N + n0 + (tx << 2)) = v;
        }
    }
}

// ---------------- edge kernel: STG to dense contrib (no atomics) ------------
__global__ __launch_bounds__(256) void edge_kernel(
    const float* __restrict__ emb_new,
    const float* __restrict__ emb_new2,
    const int*   __restrict__ edge_nodes,
    const int*   __restrict__ edge_size,
    const float* __restrict__ deg13,
    const float* __restrict__ deg14,
    const float* __restrict__ global_emb,
    const float* __restrict__ qW,
    const float* __restrict__ qb,
    float*       __restrict__ contrib)
{
    __shared__ float s_t[4][RANK];
    __shared__ float s_h[4][RANK];
    __shared__ float sge[RANK];
    const int tid = threadIdx.x;
    const int s   = tid >> 6;
    const int j   = tid & 63;

    float qw[RANK];
#pragma unroll
    for (int jj = 0; jj < RANK; jj++) qw[jj] = qW[jj * OUT_DIM + tid];
    const float qbc = qb[tid];
    if (tid < RANK) sge[tid] = global_emb[tid];
    __syncthreads();

    for (int e = blockIdx.x; e < N_EDGES; e += gridDim.x) {
        const int4 nd = ((const int4*)edge_nodes)[e];
        const int sz = edge_size[e];
        const int myn = (s == 0) ? nd.x : (s == 1) ? nd.y : (s == 2) ? nd.z : nd.w;

        float tval = 1.f;
        if (s < sz) {
            const float sc = (sz <= 3) ? deg13[myn] : deg14[myn];
            tval = sc * emb_new[(size_t)myn * RANK + j];
        }
        s_t[s][j] = tval;

        float r2 = emb_new2[(size_t)nd.x * OUT_DIM + tid]
                 + emb_new2[(size_t)nd.y * OUT_DIM + tid];
        if (sz > 2) r2 += emb_new2[(size_t)nd.z * OUT_DIM + tid];
        if (sz > 3) r2 += emb_new2[(size_t)nd.w * OUT_DIM + tid];
        r2 = fmaxf(r2, 0.f);
        __syncthreads();

        if (s < sz) {
            const int   kk   = 4 - sz;
            const float ge   = sge[j];
            const float invf = (sz == 2) ? 1.f : (sz == 3) ? 0.5f : (1.f / 6.f);
            float p = invf * ((kk == 0) ? 1.f : (kk == 1) ? ge : ge * ge);
#pragma unroll
            for (int r = 0; r < 4; r++)
                if (r != s) p *= s_t[r][j];
            s_h[s][j] = tanh_fast(p);
        }
        __syncthreads();

        // per-slot matvec (qW col in regs, h broadcast from smem) -> STG
        auto slot = [&](const float* hrow, int s2) {
            const float4* h4 = (const float4*)hrow;
            float a = qbc;
#pragma unroll
            for (int jj = 0; jj < 16; jj++) {
                float4 hv = h4[jj];
                a = fmaf(hv.x, qw[4 * jj + 0], a);
                a = fmaf(hv.y, qw[4 * jj + 1], a);
                a = fmaf(hv.z, qw[4 * jj + 2], a);
                a = fmaf(hv.w, qw[4 * jj + 3], a);
            }
            contrib[((size_t)e * 4 + s2) * OUT_DIM + tid] = a + r2;
        };
        slot(s_h[0], 0);
        slot(s_h[1], 1);
        if (sz > 2) slot(s_h[2], 2);
        if (sz > 3) slot(s_h[3], 3);

        __syncthreads();
    }
}

// ---------------- CSR build --------------------------------------------------
__global__ __launch_bounds__(1024) void prefix_kernel(
    const int* __restrict__ deg, int* __restrict__ offsets, int n)
{
    __shared__ int part[1024];
    const int t = threadIdx.x;
    const int chunk = (n + 1023) / 1024;
    const int begin = t * chunk;
    const int end   = min(begin + chunk, n);
    int s = 0;
    for (int i = begin; i < end; i++) s += deg[i];
    part[t] = s;
    __syncthreads();
    for (int off = 1; off < 1024; off <<= 1) {
        int v = (t >= off) ? part[t - off] : 0;
        __syncthreads();
        part[t] += v;
        __syncthreads();
    }
    int run = (t == 0) ? 0 : part[t - 1];
    for (int i = begin; i < end; i++) {
        offsets[i] = run;
        run += deg[i];
    }
}

__global__ void zero_int_kernel(int* __restrict__ p, int n)
{
    int i = blockIdx.x * blockDim.x + threadIdx.x;
    if (i < n) p[i] = 0;
}

__global__ void csr_fill_kernel(
    const int* __restrict__ inc_node, const int* __restrict__ inc_edge,
    const int* __restrict__ inc_slot, const int* __restrict__ offsets,
    int* __restrict__ cnt, int* __restrict__ idx_list, int m)
{
    int i = blockIdx.x * blockDim.x + threadIdx.x;
    if (i < m) {
        const int n = inc_node[i];
        const int p = offsets[n] + atomicAdd(&cnt[n], 1);
        idx_list[p] = inc_edge[i] * 4 + inc_slot[i];
    }
}

// ---------------- gather: segment-sum without atomics + finalize ------------
__global__ __launch_bounds__(256) void gather_kernel(
    const float* __restrict__ contrib,
    const int*   __restrict__ idx_list,
    const int*   __restrict__ offsets,
    const int*   __restrict__ deg,
    float*       __restrict__ out)
{
    const int gt = blockIdx.x * blockDim.x + threadIdx.x;
    const int n  = gt >> 6;                 // node
    const int c4 = (gt & 63) * 4;           // 4-col group
    if (n < N_NODES) {
        const int st = offsets[n];
        const int d  = deg[n];
        float4 acc = make_float4(0.f, 0.f, 0.f, 0.f);
        for (int k = 0; k < d; k++) {
            const int v = idx_list[st + k];
            const float4 x = *(const float4*)(contrib + (size_t)v * OUT_DIM + c4);
            acc.x += x.x; acc.y += x.y; acc.z += x.z; acc.w += x.w;
        }
        const float inv = 1.f / (float)d;
        float* op = out + (size_t)n * OUT_DIM + c4;
        float4 o = *(float4*)op;
        o.x += fmaxf(acc.x * inv, 0.f);
        o.y += fmaxf(acc.y * inv, 0.f);
        o.z += fmaxf(acc.z * inv, 0.f);
        o.w += fmaxf(acc.w * inv, 0.f);
        *(float4*)op = o;
    }
}

// ---------------- helpers ----------------------------------------------------
__global__ void round_tf32_kernel(const float* __restrict__ src,
                                  float* __restrict__ dst, int n)
{
    int i = (blockIdx.x * blockDim.x + threadIdx.x) * 4;
    if (i < n) {
        float4 v = *(const float4*)(src + i);
        v.x = to_tf32(v.x); v.y = to_tf32(v.y);
        v.z = to_tf32(v.z); v.w = to_tf32(v.w);
        *(float4*)(dst + i) = v;
    }
}

__global__ void degree_pow_kernel(const int* __restrict__ deg,
                                  float* __restrict__ d13,
                                  float* __restrict__ d14, int n)
{
    int i = blockIdx.x * blockDim.x + threadIdx.x;
    if (i < n) {
        float d = (float)deg[i];
        d13[i] = cbrtf(d);
        d14[i] = sqrtf(sqrtf(d));
    }
}

// ---------------- launch -----------------------------------------------------
extern "C" void kernel_launch(void* const* d_in, const int* in_sizes, int n_in,
                              void* d_out, int out_size)
{
    (void)n_in; (void)out_size;
    const float* embedding  = (const float*)d_in[0];
    const float* global_emb = (const float*)d_in[1];
    const float* pW   = (const float*)d_in[2];
    const float* pb   = (const float*)d_in[3];
    const float* qW   = (const float*)d_in[4];
    const float* qb   = (const float*)d_in[5];
    const float* p2W1 = (const float*)d_in[6];
    const float* p2b1 = (const float*)d_in[7];
    const float* p2W2 = (const float*)d_in[8];
    const float* p2b2 = (const float*)d_in[9];
    const float* aW   = (const float*)d_in[10];
    const float* ab   = (const float*)d_in[11];
    const int* edge_nodes  = (const int*)d_in[12];
    // d_in[13] = edge_mask (bool) — unused: mask[s] == (s < edge_size)
    const int* edge_size   = (const int*)d_in[14];
    const int* node_degree = (const int*)d_in[15];
    const int* inc_node    = (const int*)d_in[16];
    const int* inc_edge    = (const int*)d_in[17];
    const int* inc_slot    = (const int*)d_in[18];
    const int  n_inc       = in_sizes[16];
    float* out = (float*)d_out;

    float *emb_new, *hid, *emb_new2, *contrib, *embT, *w1T, *w2T, *waT, *d13, *d14;
    int *offsets, *cnt, *idx_list;
    cudaGetSymbolAddress((void**)&emb_new,  g_emb_new);
    cudaGetSymbolAddress((void**)&hid,      g_hid);
    cudaGetSymbolAddress((void**)&emb_new2, g_emb_new2);
    cudaGetSymbolAddress((void**)&contrib,  g_contrib);
    cudaGetSymbolAddress((void**)&embT,     g_embT);
    cudaGetSymbolAddress((void**)&w1T,      g_w1T);
    cudaGetSymbolAddress((void**)&w2T,      g_w2T);
    cudaGetSymbolAddress((void**)&waT,      g_waT);
    cudaGetSymbolAddress((void**)&d13,      g_deg13);
    cudaGetSymbolAddress((void**)&d14,      g_deg14);
    cudaGetSymbolAddress((void**)&offsets,  g_offsets);
    cudaGetSymbolAddress((void**)&cnt,      g_cnt);
    cudaGetSymbolAddress((void**)&idx_list, g_idx);

    cudaFuncSetAttribute(gemm_tf32_kernel,
                         cudaFuncAttributeMaxDynamicSharedMemorySize,
                         GEMM_SMEM_BYTES);

    dim3 blk(256);
    const int mby64  = (N_NODES + TM - 1) / TM;
    const int mby128 = (N_NODES + 127) / 128;

    // ---- CSR build (independent of GEMMs) ----
    prefix_kernel<<<1, 1024>>>(node_degree, offsets, N_NODES);
    zero_int_kernel<<<(N_NODES + 255) / 256, blk>>>(cnt, N_NODES);
    csr_fill_kernel<<<(n_inc + 255) / 256, blk>>>(
        inc_node, inc_edge, inc_slot, offsets, cnt, idx_list, n_inc);

    // ---- pre-pass: tf32-round operands, precompute degree powers ----
    round_tf32_kernel<<<(N_NODES * FEAT / 4 + 255) / 256, blk>>>(
        embedding, embT, N_NODES * FEAT);
    round_tf32_kernel<<<(FEAT * HID / 4 + 255) / 256, blk>>>(
        p2W1, w1T, FEAT * HID);
    round_tf32_kernel<<<(HID * OUT_DIM / 4 + 255) / 256, blk>>>(
        p2W2, w2T, HID * OUT_DIM);
    round_tf32_kernel<<<(FEAT * OUT_DIM / 4 + 255) / 256, blk>>>(
        aW, waT, FEAT * OUT_DIM);
    degree_pow_kernel<<<(N_NODES + 255) / 256, blk>>>(
        node_degree, d13, d14, N_NODES);

    // emb_new = embedding @ pW[:256] + pW[256] + pb   (fp32: accuracy-critical)
    gemm64_kernel<<<dim3(RANK / TN, mby64), blk>>>(
        embedding, pW, pb, pW + (size_t)FEAT * RANK,
        emb_new, N_NODES, RANK, FEAT, 0);
    // hid = relu(embT @ w1T + p2W1[256] + p2b1), rounded to tf32
    gemm_tf32_kernel<<<dim3(HID / 128, mby128), blk, GEMM_SMEM_BYTES>>>(
        embT, w1T, p2b1, p2W1 + (size_t)FEAT * HID,
        hid, N_NODES, HID, FEAT, 1 | 2);
    // emb_new2 = hid @ w2T + p2b2
    gemm_tf32_kernel<<<dim3(OUT_DIM / 128, mby128), blk, GEMM_SMEM_BYTES>>>(
        hid, w2T, p2b2, nullptr,
        emb_new2, N_NODES, OUT_DIM, HID, 0);
    // residual = relu(embT @ waT + aW[256] + ab) -> d_out
    gemm_tf32_kernel<<<dim3(OUT_DIM / 128, mby128), blk, GEMM_SMEM_BYTES>>>(
        embT, waT, ab, aW + (size_t)FEAT * OUT_DIM,
        out, N_NODES, OUT_DIM, FEAT, 1);

    // per-incidence contributions (STG, no atomics)
    edge_kernel<<<1480, blk>>>(emb_new, emb_new2, edge_nodes, edge_size,
                               d13, d14, global_emb, qW, qb, contrib);

    // atomic-free segment sum + finalize
    gather_kernel<<<(N_NODES * 64 + 255) / 256, blk>>>(
        contrib, idx_list, offsets, node_degree, out);
}

// round 13
// speedup vs baseline: 1.1667x; 1.1667x over previous
#include <cuda_runtime.h>
#include <math.h>
#include <stdint.h>

#define N_NODES 30000
#define N_EDGES 60000
#define FEAT    256
#define HID     1024
#define OUT_DIM 256
#define RANK    64
#define MAX_INC (N_EDGES * 4)
#define N_INC_ROWS (N_EDGES * 4)      // 240000, == 128 * 1875

// ---------------- scratch (static device globals; no runtime allocation) ----
__device__ float g_emb_new [(size_t)N_NODES * RANK];
__device__ float g_hid     [(size_t)N_NODES * HID];
__device__ float g_emb_new2[(size_t)N_NODES * OUT_DIM];
__device__ float g_contrib [(size_t)N_INC_ROWS * OUT_DIM];   // 245.8 MB
__device__ float g_hinc    [(size_t)N_INC_ROWS * RANK];      // 61.4 MB
__device__ float g_r2      [(size_t)N_EDGES * OUT_DIM];      // 61.4 MB
__device__ float g_embT    [(size_t)N_NODES * FEAT];
__device__ float g_w1T     [(size_t)FEAT * HID];
__device__ float g_w2T     [(size_t)HID * OUT_DIM];
__device__ float g_waT     [(size_t)FEAT * OUT_DIM];
__device__ float g_qwT     [(size_t)RANK * OUT_DIM];
__device__ float g_deg13   [N_NODES];
__device__ float g_deg14   [N_NODES];
__device__ int   g_offsets [N_NODES];
__device__ int   g_cnt     [N_NODES];
__device__ int   g_idx     [MAX_INC];

__device__ __forceinline__ float tanh_fast(float x)
{
    float y;
    asm("tanh.approx.f32 %0, %1;" : "=f"(y) : "f"(x));
    return y;
}

__device__ __forceinline__ float to_tf32(float x)
{
    uint32_t u;
    asm("cvt.rna.tf32.f32 %0, %1;" : "=r"(u) : "f"(x));
    return __uint_as_float(u);
}

__device__ __forceinline__ void mma_tf32(float d[4], const uint32_t a[4],
                                         const uint32_t b[2])
{
    asm("mma.sync.aligned.m16n8k8.row.col.f32.tf32.tf32.f32 "
        "{%0,%1,%2,%3}, {%4,%5,%6,%7}, {%8,%9}, {%0,%1,%2,%3};"
        : "+f"(d[0]), "+f"(d[1]), "+f"(d[2]), "+f"(d[3])
        : "r"(a[0]), "r"(a[1]), "r"(a[2]), "r"(a[3]),
          "r"(b[0]), "r"(b[1]));
}

__device__ __forceinline__ void cp16(uint32_t dst, const float* src, bool valid)
{
    asm volatile("cp.async.cg.shared.global [%0], [%1], 16, %2;\n"
                 :: "r"(dst), "l"(src), "r"(valid ? 16 : 0));
}
__device__ __forceinline__ void cp_commit()
{
    asm volatile("cp.async.commit_group;\n");
}
template <int N> __device__ __forceinline__ void cp_wait()
{
    asm volatile("cp.async.wait_group %0;\n" :: "n"(N));
}

// ===== tf32 tensor GEMM: cp.async 2-stage, operands pre-rounded =============
// C = act(A @ W[:K] + wrow + bias [+ r2inc]); block 128x128, BK=32, 8 warps.
// flags: bit0 relu, bit1 round output to tf32.
// r2inc (optional): per-incidence extra bias, r2inc[(row>>2)*N + col].
#define AS_STRIDE 36
#define BS_STRIDE 132
#define AS_SZ (128 * AS_STRIDE)
#define BS_SZ (32 * BS_STRIDE)
#define GEMM_SMEM_BYTES ((2 * AS_SZ + 2 * BS_SZ) * 4)

__global__ __launch_bounds__(256, 2) void gemm_tf32_kernel(
    const float* __restrict__ A, const float* __restrict__ W,
    const float* __restrict__ bias, const float* __restrict__ wrow,
    const float* __restrict__ r2inc,
    float* __restrict__ C, int M, int N, int K, int flags)
{
    extern __shared__ float sh[];
    const uint32_t sbase = (uint32_t)__cvta_generic_to_shared(sh);

    const int tid    = threadIdx.x;
    const int lane   = tid & 31;
    const int w      = tid >> 5;
    const int warp_m = w & 1;
    const int warp_n = w >> 1;
    const int g      = lane >> 2;
    const int tg     = lane & 3;
    const int m0     = blockIdx.y * 128;
    const int n0     = blockIdx.x * 128;

    const int a_r  = tid >> 1;
    const int a_c  = (tid & 1) * 16;
    const int b_r  = tid >> 3;
    const int b_c  = (tid & 7) * 16;
    const bool a_ok = (m0 + a_r) < M;

    auto load_tile = [&](int buf, int k0) {
        const uint32_t aoff = sbase +
            (uint32_t)(buf * AS_SZ + a_r * AS_STRIDE + a_c) * 4;
        const float* asrc = A + (size_t)(m0 + a_r) * K + k0 + a_c;
#pragma unroll
        for (int i = 0; i < 4; i++)
            cp16(aoff + 16 * i, asrc + 4 * i, a_ok);
        const uint32_t boff = sbase +
            (uint32_t)(2 * AS_SZ + buf * BS_SZ + b_r * BS_STRIDE + b_c) * 4;
        const float* bsrc = W + (size_t)(k0 + b_r) * N + n0 + b_c;
#pragma unroll
        for (int i = 0; i < 4; i++)
            cp16(boff + 16 * i, bsrc + 4 * i, true);
    };

    float d[4][4][4];
#pragma unroll
    for (int i = 0; i < 4; i++)
#pragma unroll
        for (int j = 0; j < 4; j++)
#pragma unroll
            for (int c = 0; c < 4; c++) d[i][j][c] = 0.f;

    load_tile(0, 0);
    cp_commit();

    int buf = 0;
    for (int k0 = 0; k0 < K; k0 += 32) {
        const bool more = (k0 + 32) < K;
        if (more) { load_tile(buf ^ 1, k0 + 32); cp_commit(); cp_wait<1>(); }
        else      { cp_wait<0>(); }
        __syncthreads();

        const float* Ab = sh + buf * AS_SZ;
        const float* Bb = sh + 2 * AS_SZ + buf * BS_SZ;
#pragma unroll
        for (int ks8 = 0; ks8 < 4; ks8++) {
            const int ks = ks8 * 8;
            uint32_t af[4][4], bf[4][2];
#pragma unroll
            for (int mg = 0; mg < 4; mg++) {
                const int r = warp_m * 64 + mg * 16 + g;
                af[mg][0] = __float_as_uint(Ab[r * AS_STRIDE + ks + tg]);
                af[mg][1] = __float_as_uint(Ab[(r + 8) * AS_STRIDE + ks + tg]);
                af[mg][2] = __float_as_uint(Ab[r * AS_STRIDE + ks + tg + 4]);
                af[mg][3] = __float_as_uint(Ab[(r + 8) * AS_STRIDE + ks + tg + 4]);
            }
#pragma unroll
            for (int ng = 0; ng < 4; ng++) {
                const int cc = warp_n * 32 + ng * 8 + g;
                bf[ng][0] = __float_as_uint(Bb[(ks + tg) * BS_STRIDE + cc]);
                bf[ng][1] = __float_as_uint(Bb[(ks + tg + 4) * BS_STRIDE + cc]);
            }
#pragma unroll
            for (int mg = 0; mg < 4; mg++)
#pragma unroll
                for (int ng = 0; ng < 4; ng++)
                    mma_tf32(d[mg][ng], af[mg], bf[ng]);
        }
        __syncthreads();
        buf ^= 1;
    }

    const bool do_relu  = flags & 1;
    const bool do_round = flags & 2;
#pragma unroll
    for (int mg = 0; mg < 4; mg++) {
        const int r0 = m0 + warp_m * 64 + mg * 16 + g;
#pragma unroll
        for (int ng = 0; ng < 4; ng++) {
            const int col = n0 + warp_n * 32 + ng * 8 + tg * 2;
            float b0 = bias[col]     + (wrow ? wrow[col]     : 0.f);
            float b1 = bias[col + 1] + (wrow ? wrow[col + 1] : 0.f);
            float v0 = d[mg][ng][0] + b0;
            float v1 = d[mg][ng][1] + b1;
            float v2 = d[mg][ng][2] + b0;
            float v3 = d[mg][ng][3] + b1;
            if (r2inc) {
                const float* rA = r2inc + (size_t)(r0 >> 2) * N + col;
                const float* rB = r2inc + (size_t)((r0 + 8) >> 2) * N + col;
                v0 += rA[0]; v1 += rA[1];
                v2 += rB[0]; v3 += rB[1];
            }
            if (do_relu) {
                v0 = fmaxf(v0, 0.f); v1 = fmaxf(v1, 0.f);
                v2 = fmaxf(v2, 0.f); v3 = fmaxf(v3, 0.f);
            }
            if (do_round) {
                v0 = to_tf32(v0); v1 = to_tf32(v1);
                v2 = to_tf32(v2); v3 = to_tf32(v3);
            }
            if (r0 < M)
                *(float2*)(C + (size_t)r0 * N + col) = make_float2(v0, v1);
            if (r0 + 8 < M)
                *(float2*)(C + (size_t)(r0 + 8) * N + col) = make_float2(v2, v3);
        }
    }
}

// ---------------- 64x64 fp32 SGEMM (pW only: accuracy-critical path) --------
#define TM 64
#define TN 64
#define TK 16
#define SST 72

__global__ __launch_bounds__(256) void gemm64_kernel(
    const float* __restrict__ A, const float* __restrict__ W,
    const float* __restrict__ bias, const float* __restrict__ wrow,
    float* __restrict__ C, int M, int N, int K, int do_relu)
{
    __shared__ float As[TK][SST];
    __shared__ float Bs[TK][SST];
    const int tid = threadIdx.x;
    const int tx  = tid & 15;
    const int ty  = tid >> 4;
    const int m0  = blockIdx.y * TM;
    const int n0  = blockIdx.x * TN;

    const int arow = tid >> 2;
    const int acol = (tid & 3) << 2;
    const int brow = tid >> 4;
    const int bcol = (tid & 15) << 2;

    float acc[4][4] = {{0.f,0.f,0.f,0.f},{0.f,0.f,0.f,0.f},
                       {0.f,0.f,0.f,0.f},{0.f,0.f,0.f,0.f}};

    for (int k0 = 0; k0 < K; k0 += TK) {
        float4 av = make_float4(0.f, 0.f, 0.f, 0.f);
        if (m0 + arow < M)
            av = *(const float4*)(A + (size_t)(m0 + arow) * K + k0 + acol);
        As[acol + 0][arow] = av.x;
        As[acol + 1][arow] = av.y;
        As[acol + 2][arow] = av.z;
        As[acol + 3][arow] = av.w;
        *(float4*)&Bs[brow][bcol] =
            *(const float4*)(W + (size_t)(k0 + brow) * N + n0 + bcol);
        __syncthreads();
#pragma unroll
        for (int k = 0; k < TK; k++) {
            float4 a = *(const float4*)&As[k][ty << 2];
            float4 b = *(const float4*)&Bs[k][tx << 2];
            acc[0][0] = fmaf(a.x, b.x, acc[0][0]);
            acc[0][1] = fmaf(a.x, b.y, acc[0][1]);
            acc[0][2] = fmaf(a.x, b.z, acc[0][2]);
            acc[0][3] = fmaf(a.x, b.w, acc[0][3]);
            acc[1][0] = fmaf(a.y, b.x, acc[1][0]);
            acc[1][1] = fmaf(a.y, b.y, acc[1][1]);
            acc[1][2] = fmaf(a.y, b.z, acc[1][2]);
            acc[1][3] = fmaf(a.y, b.w, acc[1][3]);
            acc[2][0] = fmaf(a.z, b.x, acc[2][0]);
            acc[2][1] = fmaf(a.z, b.y, acc[2][1]);
            acc[2][2] = fmaf(a.z, b.z, acc[2][2]);
            acc[2][3] = fmaf(a.z, b.w, acc[2][3]);
            acc[3][0] = fmaf(a.w, b.x, acc[3][0]);
            acc[3][1] = fmaf(a.w, b.y, acc[3][1]);
            acc[3][2] = fmaf(a.w, b.z, acc[3][2]);
            acc[3][3] = fmaf(a.w, b.w, acc[3][3]);
        }
        __syncthreads();
    }

    float bn[4];
#pragma unroll
    for (int j = 0; j < 4; j++) {
        int n = n0 + (tx << 2) + j;
        bn[j] = bias[n] + (wrow ? wrow[n] : 0.f);
    }
#pragma unroll
    for (int i = 0; i < 4; i++) {
        int m = m0 + (ty << 2) + i;
        if (m < M) {
            float4 v;
            v.x = acc[i][0] + bn[0];
            v.y = acc[i][1] + bn[1];
            v.z = acc[i][2] + bn[2];
            v.w = acc[i][3] + bn[3];
            if (do_relu) {
                v.x = fmaxf(v.x, 0.f); v.y = fmaxf(v.y, 0.f);
                v.z = fmaxf(v.z, 0.f); v.w = fmaxf(v.w, 0.f);
            }
            *(float4*)(C + (size_t)m * N + n0 + (tx << 2)) = v;
        }
    }
}

// ---------------- h kernel: per-incidence tanh features ---------------------
// h[(e*4+s)*RANK + j] = tf32(tanh(gf * prod_{r!=s} t_r[j]))
__global__ __launch_bounds__(256) void h_kernel(
    const float* __restrict__ emb_new,
    const int*   __restrict__ edge_nodes,
    const int*   __restrict__ edge_size,
    const float* __restrict__ deg13,
    const float* __restrict__ deg14,
    const float* __restrict__ global_emb,
    float*       __restrict__ hout)
{
    __shared__ float s_t[4][RANK];
    __shared__ float sge[RANK];
    const int tid = threadIdx.x;
    const int s   = tid >> 6;
    const int j   = tid & 63;

    if (tid < RANK) sge[tid] = global_emb[tid];
    __syncthreads();

    for (int e = blockIdx.x; e < N_EDGES; e += gridDim.x) {
        const int4 nd = ((const int4*)edge_nodes)[e];
        const int sz = edge_size[e];
        const int myn = (s == 0) ? nd.x : (s == 1) ? nd.y : (s == 2) ? nd.z : nd.w;

        float tval = 1.f;
        if (s < sz) {
            const float sc = (sz <= 3) ? deg13[myn] : deg14[myn];
            tval = sc * emb_new[(size_t)myn * RANK + j];
        }
        s_t[s][j] = tval;
        __syncthreads();

        const int   kk   = 4 - sz;
        const float ge   = sge[j];
        const float invf = (sz == 2) ? 1.f : (sz == 3) ? 0.5f : (1.f / 6.f);
        float p = invf * ((kk == 0) ? 1.f : (kk == 1) ? ge : ge * ge);
#pragma unroll
        for (int r = 0; r < 4; r++)
            if (r != s) p *= s_t[r][j];
        hout[((size_t)e * 4 + s) * RANK + j] = to_tf32(tanh_fast(p));
        __syncthreads();
    }
}

// ---------------- r2 kernel: per-edge relu'd emb_new2 sum -------------------
__global__ __launch_bounds__(256) void r2_kernel(
    const float* __restrict__ emb_new2,
    const int*   __restrict__ edge_nodes,
    const int*   __restrict__ edge_size,
    float*       __restrict__ r2out)
{
    const int e   = blockIdx.x;
    const int col = threadIdx.x;
    const int4 nd = ((const int4*)edge_nodes)[e];
    const int sz  = edge_size[e];
    float r = emb_new2[(size_t)nd.x * OUT_DIM + col]
            + emb_new2[(size_t)nd.y * OUT_DIM + col];
    if (sz > 2) r += emb_new2[(size_t)nd.z * OUT_DIM + col];
    if (sz > 3) r += emb_new2[(size_t)nd.w * OUT_DIM + col];
    r2out[(size_t)e * OUT_DIM + col] = fmaxf(r, 0.f);
}

// ---------------- CSR build --------------------------------------------------
__global__ __launch_bounds__(1024) void prefix_kernel(
    const int* __restrict__ deg, int* __restrict__ offsets, int n)
{
    __shared__ int part[1024];
    const int t = threadIdx.x;
    const int chunk = (n + 1023) / 1024;
    const int begin = t * chunk;
    const int end   = min(begin + chunk, n);
    int s = 0;
    for (int i = begin; i < end; i++) s += deg[i];
    part[t] = s;
    __syncthreads();
    for (int off = 1; off < 1024; off <<= 1) {
        int v = (t >= off) ? part[t - off] : 0;
        __syncthreads();
        part[t] += v;
        __syncthreads();
    }
    int run = (t == 0) ? 0 : part[t - 1];
    for (int i = begin; i < end; i++) {
        offsets[i] = run;
        run += deg[i];
    }
}

__global__ void zero_int_kernel(int* __restrict__ p, int n)
{
    int i = blockIdx.x * blockDim.x + threadIdx.x;
    if (i < n) p[i] = 0;
}

__global__ void csr_fill_kernel(
    const int* __restrict__ inc_node, const int* __restrict__ inc_edge,
    const int* __restrict__ inc_slot, const int* __restrict__ offsets,
    int* __restrict__ cnt, int* __restrict__ idx_list, int m)
{
    int i = blockIdx.x * blockDim.x + threadIdx.x;
    if (i < m) {
        const int n = inc_node[i];
        const int p = offsets[n] + atomicAdd(&cnt[n], 1);
        idx_list[p] = inc_edge[i] * 4 + inc_slot[i];
    }
}

// ---------------- gather: segment-sum without atomics + finalize ------------
__global__ __launch_bounds__(256) void gather_kernel(
    const float* __restrict__ contrib,
    const int*   __restrict__ idx_list,
    const int*   __restrict__ offsets,
    const int*   __restrict__ deg,
    float*       __restrict__ out)
{
    const int gt = blockIdx.x * blockDim.x + threadIdx.x;
    const int n  = gt >> 6;
    const int c4 = (gt & 63) * 4;
    if (n < N_NODES) {
        const int st = offsets[n];
        const int d  = deg[n];
        float4 acc = make_float4(0.f, 0.f, 0.f, 0.f);
        for (int k = 0; k < d; k++) {
            const int v = idx_list[st + k];
            const float4 x = *(const float4*)(contrib + (size_t)v * OUT_DIM + c4);
            acc.x += x.x; acc.y += x.y; acc.z += x.z; acc.w += x.w;
        }
        const float inv = 1.f / (float)d;
        float* op = out + (size_t)n * OUT_DIM + c4;
        float4 o = *(float4*)op;
        o.x += fmaxf(acc.x * inv, 0.f);
        o.y += fmaxf(acc.y * inv, 0.f);
        o.z += fmaxf(acc.z * inv, 0.f);
        o.w += fmaxf(acc.w * inv, 0.f);
        *(float4*)op = o;
    }
}

// ---------------- helpers ----------------------------------------------------
__global__ void round_tf32_kernel(const float* __restrict__ src,
                                  float* __restrict__ dst, int n)
{
    int i = (blockIdx.x * blockDim.x + threadIdx.x) * 4;
    if (i < n) {
        float4 v = *(const float4*)(src + i);
        v.x = to_tf32(v.x); v.y = to_tf32(v.y);
        v.z = to_tf32(v.z); v.w = to_tf32(v.w);
        *(float4*)(dst + i) = v;
    }
}

__global__ void degree_pow_kernel(const int* __restrict__ deg,
                                  float* __restrict__ d13,
                                  float* __restrict__ d14, int n)
{
    int i = blockIdx.x * blockDim.x + threadIdx.x;
    if (i < n) {
        float d = (float)deg[i];
        d13[i] = cbrtf(d);
        d14[i] = sqrtf(sqrtf(d));
    }
}

// ---------------- launch -----------------------------------------------------
extern "C" void kernel_launch(void* const* d_in, const int* in_sizes, int n_in,
                              void* d_out, int out_size)
{
    (void)n_in; (void)out_size;
    const float* embedding  = (const float*)d_in[0];
    const float* global_emb = (const float*)d_in[1];
    const float* pW   = (const float*)d_in[2];
    const float* pb   = (const float*)d_in[3];
    const float* qW   = (const float*)d_in[4];
    const float* qb   = (const float*)d_in[5];
    const float* p2W1 = (const float*)d_in[6];
    const float* p2b1 = (const float*)d_in[7];
    const float* p2W2 = (const float*)d_in[8];
    const float* p2b2 = (const float*)d_in[9];
    const float* aW   = (const float*)d_in[10];
    const float* ab   = (const float*)d_in[11];
    const int* edge_nodes  = (const int*)d_in[12];
    // d_in[13] = edge_mask (bool) — unused: mask[s] == (s < edge_size)
    const int* edge_size   = (const int*)d_in[14];
    const int* node_degree = (const int*)d_in[15];
    const int* inc_node    = (const int*)d_in[16];
    const int* inc_edge    = (const int*)d_in[17];
    const int* inc_slot    = (const int*)d_in[18];
    const int  n_inc       = in_sizes[16];
    float* out = (float*)d_out;

    float *emb_new, *hid, *emb_new2, *contrib, *hinc, *r2;
    float *embT, *w1T, *w2T, *waT, *qwT, *d13, *d14;
    int *offsets, *cnt, *idx_list;
    cudaGetSymbolAddress((void**)&emb_new,  g_emb_new);
    cudaGetSymbolAddress((void**)&hid,      g_hid);
    cudaGetSymbolAddress((void**)&emb_new2, g_emb_new2);
    cudaGetSymbolAddress((void**)&contrib,  g_contrib);
    cudaGetSymbolAddress((void**)&hinc,     g_hinc);
    cudaGetSymbolAddress((void**)&r2,       g_r2);
    cudaGetSymbolAddress((void**)&embT,     g_embT);
    cudaGetSymbolAddress((void**)&w1T,      g_w1T);
    cudaGetSymbolAddress((void**)&w2T,      g_w2T);
    cudaGetSymbolAddress((void**)&waT,      g_waT);
    cudaGetSymbolAddress((void**)&qwT,      g_qwT);
    cudaGetSymbolAddress((void**)&d13,      g_deg13);
    cudaGetSymbolAddress((void**)&d14,      g_deg14);
    cudaGetSymbolAddress((void**)&offsets,  g_offsets);
    cudaGetSymbolAddress((void**)&cnt,      g_cnt);
    cudaGetSymbolAddress((void**)&idx_list, g_idx);

    cudaFuncSetAttribute(gemm_tf32_kernel,
                         cudaFuncAttributeMaxDynamicSharedMemorySize,
                         GEMM_SMEM_BYTES);

    dim3 blk(256);
    const int mby64  = (N_NODES + TM - 1) / TM;
    const int mby128 = (N_NODES + 127) / 128;

    // ---- CSR build ----
    prefix_kernel<<<1, 1024>>>(node_degree, offsets, N_NODES);
    zero_int_kernel<<<(N_NODES + 255) / 256, blk>>>(cnt, N_NODES);
    csr_fill_kernel<<<(n_inc + 255) / 256, blk>>>(
        inc_node, inc_edge, inc_slot, offsets, cnt, idx_list, n_inc);

    // ---- pre-pass: tf32-round operands, precompute degree powers ----
    round_tf32_kernel<<<(N_NODES * FEAT / 4 + 255) / 256, blk>>>(
        embedding, embT, N_NODES * FEAT);
    round_tf32_kernel<<<(FEAT * HID / 4 + 255) / 256, blk>>>(
        p2W1, w1T, FEAT * HID);
    round_tf32_kernel<<<(HID * OUT_DIM / 4 + 255) / 256, blk>>>(
        p2W2, w2T, HID * OUT_DIM);
    round_tf32_kernel<<<(FEAT * OUT_DIM / 4 + 255) / 256, blk>>>(
        aW, waT, FEAT * OUT_DIM);
    round_tf32_kernel<<<(RANK * OUT_DIM / 4 + 255) / 256, blk>>>(
        qW, qwT, RANK * OUT_DIM);
    degree_pow_kernel<<<(N_NODES + 255) / 256, blk>>>(
        node_degree, d13, d14, N_NODES);

    // emb_new = embedding @ pW[:256] + pW[256] + pb   (fp32: accuracy-critical)
    gemm64_kernel<<<dim3(RANK / TN, mby64), blk>>>(
        embedding, pW, pb, pW + (size_t)FEAT * RANK,
        emb_new, N_NODES, RANK, FEAT, 0);
    // hid = relu(embT @ w1T + p2W1[256] + p2b1), rounded to tf32
    gemm_tf32_kernel<<<dim3(HID / 128, mby128), blk, GEMM_SMEM_BYTES>>>(
        embT, w1T, p2b1, p2W1 + (size_t)FEAT * HID, nullptr,
        hid, N_NODES, HID, FEAT, 1 | 2);
    // emb_new2 = hid @ w2T + p2b2
    gemm_tf32_kernel<<<dim3(OUT_DIM / 128, mby128), blk, GEMM_SMEM_BYTES>>>(
        hid, w2T, p2b2, nullptr, nullptr,
        emb_new2, N_NODES, OUT_DIM, HID, 0);
    // residual = relu(embT @ waT + aW[256] + ab) -> d_out
    gemm_tf32_kernel<<<dim3(OUT_DIM / 128, mby128), blk, GEMM_SMEM_BYTES>>>(
        embT, waT, ab, aW + (size_t)FEAT * OUT_DIM, nullptr,
        out, N_NODES, OUT_DIM, FEAT, 1);

    // per-incidence tanh features
    h_kernel<<<1480, blk>>>(emb_new, edge_nodes, edge_size,
                            d13, d14, global_emb, hinc);
    // per-edge relu'd emb_new2 sums
    r2_kernel<<<N_EDGES, blk>>>(emb_new2, edge_nodes, edge_size, r2);

    // contrib = hinc @ qwT + qb + r2[row>>2]   (tensor GEMM, M = 240000)
    gemm_tf32_kernel<<<dim3(OUT_DIM / 128, N_INC_ROWS / 128), blk,
                      GEMM_SMEM_BYTES>>>(
        hinc, qwT, qb, nullptr, r2,
        contrib, N_INC_ROWS, OUT_DIM, RANK, 0);

    // atomic-free segment sum + finalize
    gather_kernel<<<(N_NODES * 64 + 255) / 256, blk>>>(
        contrib, idx_list, offsets, node_degree, out);
}